// round 9
// baseline (speedup 1.0000x reference)
#include <cuda_runtime.h>
#include <cuda_fp16.h>
#include <stdint.h>

// Problem constants (fixed by setup_inputs)
#define NQ   100000
#define HN   32      // neighbors per query
#define KP   15      // kernel points
#define CIN  64
#define COUT 128
#define KC   (KP * CIN)   // 960
#define MAXM 100000  // support points (fixed by setup_inputs)
#define KP_EXT 1.2f
#define KP_EXT2 (KP_EXT * KP_EXT)   // 1.44

// Scratch (device globals: allocation-free)
__device__ __half g_weighted[(size_t)NQ * KC];   // [N][K*Cin] fp16, ~192 MB
__device__ __half g_wts[KC * COUT];              // [K*Cin][Cout] fp16
__device__ float4 g_spts4[MAXM];                 // padded support points, 1.6 MB

__device__ __forceinline__ uint32_t smem_u32(const void* p) {
    uint32_t a;
    asm("{ .reg .u64 t; cvta.to.shared.u64 t, %1; cvt.u32.u64 %0, t; }"
        : "=r"(a) : "l"(p));
    return a;
}

// ---------------------------------------------------------------------------
// Kernel 0: prep — wts fp32->fp16 AND float4-padded support points.
// (g_spts4 turns the weight kernel's 3 scattered scalar LDGs per lane into
//  one LDG.128, ~ -60 L1 wavefronts per query.)
// ---------------------------------------------------------------------------
__global__ void prep_kernel(const float* __restrict__ wts,
                            const float* __restrict__ spts, int m) {
    int i = blockIdx.x * blockDim.x + threadIdx.x;
    if (i < KC * COUT) g_wts[i] = __float2half(wts[i]);
    if (i < m)
        g_spts4[i] = make_float4(spts[3 * i + 0], spts[3 * i + 1],
                                 spts[3 * i + 2], 0.0f);
}

// ---------------------------------------------------------------------------
// Kernel 1: weights + sparse weighted feature aggregation.
// vs round 8: float4 spts gather, set-bit staging walk, HFMA2 accumulation
// (w packed half2, features half2 -> 5 instr / active pair instead of 8).
// ---------------------------------------------------------------------------
__global__ void __launch_bounds__(128, 12) weight_kernel(
    const float* __restrict__ qpts,
    const int*   __restrict__ nidx,
    const float* __restrict__ feats,
    const float* __restrict__ kpts,
    int nq)
{
    __shared__ __half2 Fs[4][HN * 32];  // [warp][h][c-pair]  4*4KB = 16KB
    __shared__ float4 skp[KP];          // (kx, ky, kz, |kp|^2)

    int tid = threadIdx.x;
    if (tid < KP) {
        float kx = kpts[3 * tid + 0];
        float ky = kpts[3 * tid + 1];
        float kz = kpts[3 * tid + 2];
        skp[tid] = make_float4(kx, ky, kz, kx * kx + ky * ky + kz * kz);
    }
    __syncthreads();

    int warp = tid >> 5;
    int lane = tid & 31;
    const float inv_ext = 1.0f / KP_EXT;
    int qbase = blockIdx.x * 16 + warp * 4;

    const float2* __restrict__ f2 = (const float2*)feats;
    __half2* FsW = Fs[warp];
    __half2* outp = (__half2*)g_weighted;

    #pragma unroll 1
    for (int qi = 0; qi < 4; qi++) {
        int q = qbase + qi;
        if (q >= nq) return;   // warp-uniform

        // ---- weights: lane owns neighbor h = lane ----
        int idx = nidx[q * HN + lane];
        float4 sp = g_spts4[idx];                  // single LDG.128
        float qx = qpts[q * 3 + 0];
        float qy = qpts[q * 3 + 1];
        float qz = qpts[q * 3 + 2];
        float px = sp.x - qx;
        float py = sp.y - qy;
        float pz = sp.z - qz;
        float pp = px * px + py * py + pz * pz;

        uint32_t w2[KP];                           // half2(w, w)
        unsigned m[KP];
        unsigned active_h = 0;
        #pragma unroll
        for (int k = 0; k < KP; k++) {
            float4 kv = skp[k];
            float t  = fmaf(px, kv.x, fmaf(py, kv.y, pz * kv.z));
            float d2 = fmaf(-2.0f, t, pp + kv.w);
            float wv = 0.0f;
            if (d2 < KP_EXT2)
                wv = 1.0f - sqrtf(fmaxf(d2, 0.0f)) * inv_ext;
            __half2 wh = __floats2half2_rn(wv, wv);
            w2[k] = *reinterpret_cast<uint32_t*>(&wh);
            m[k] = __ballot_sync(0xffffffffu, wv > 0.0f);
            active_h |= m[k];
        }

        // ---- Phase A: stage active neighbor features (set-bit walk) ----
        __syncwarp();
        unsigned aa = active_h;
        while (aa) {
            int h = __ffs(aa) - 1;
            aa &= aa - 1;
            int ih = __shfl_sync(0xffffffffu, idx, h);
            float2 f = f2[(size_t)ih * 32 + lane];
            FsW[h * 32 + lane] = __floats2half2_rn(f.x, f.y);
        }
        __syncwarp();

        // ---- Phase B: sparse per-k accumulation (fp16 HFMA2) ----
        #pragma unroll
        for (int k = 0; k < KP; k++) {
            __half2 acc = __floats2half2_rn(0.0f, 0.0f);
            unsigned mm = m[k];
            while (mm) {
                int h = __ffs(mm) - 1;
                mm &= mm - 1;
                uint32_t wk = __shfl_sync(0xffffffffu, w2[k], h);
                acc = __hfma2(*reinterpret_cast<__half2*>(&wk),
                              FsW[h * 32 + lane], acc);
            }
            outp[(size_t)q * (KC / 2) + k * 32 + lane] = acc;
        }
    }
}

// ---------------------------------------------------------------------------
// Kernel 2: GEMM out[N][128] = weighted[N][960] (f16) x wts[960][128] (f16)
// 128x128 tile, 8 warps (64x32 each), m16n8k16 HMMA, 2-stage cp.async pipeline.
// ---------------------------------------------------------------------------
__device__ __forceinline__ void ldm_x4(uint32_t& r0, uint32_t& r1,
                                       uint32_t& r2, uint32_t& r3,
                                       uint32_t addr) {
    asm volatile("ldmatrix.sync.aligned.m8n8.x4.shared.b16 {%0,%1,%2,%3}, [%4];"
                 : "=r"(r0), "=r"(r1), "=r"(r2), "=r"(r3) : "r"(addr));
}
__device__ __forceinline__ void ldm_x4_t(uint32_t& r0, uint32_t& r1,
                                         uint32_t& r2, uint32_t& r3,
                                         uint32_t addr) {
    asm volatile("ldmatrix.sync.aligned.m8n8.x4.trans.shared.b16 {%0,%1,%2,%3}, [%4];"
                 : "=r"(r0), "=r"(r1), "=r"(r2), "=r"(r3) : "r"(addr));
}
__device__ __forceinline__ void mma16816(float& c0, float& c1, float& c2, float& c3,
                                         uint32_t a0, uint32_t a1, uint32_t a2, uint32_t a3,
                                         uint32_t b0, uint32_t b1) {
    asm volatile(
        "mma.sync.aligned.m16n8k16.row.col.f32.f16.f16.f32 "
        "{%0,%1,%2,%3}, {%4,%5,%6,%7}, {%8,%9}, {%0,%1,%2,%3};"
        : "+f"(c0), "+f"(c1), "+f"(c2), "+f"(c3)
        : "r"(a0), "r"(a1), "r"(a2), "r"(a3), "r"(b0), "r"(b1));
}
__device__ __forceinline__ void cp16(uint32_t dst, const void* src, bool pred) {
    int sz = pred ? 16 : 0;
    asm volatile("cp.async.cg.shared.global [%0], [%1], 16, %2;"
                 :: "r"(dst), "l"(src), "r"(sz) : "memory");
}

#define AS_STRIDE 48    // halves per A row (32 data + 16 pad)
#define BS_STRIDE 136   // halves per B row (128 data + 8 pad)
#define NKT (KC / 32)   // 30 k-iterations

__global__ void __launch_bounds__(256) gemm_kernel(float* __restrict__ out, int nq) {
    __shared__ __half As[2][128 * AS_STRIDE];
    __shared__ __half Bs[2][32 * BS_STRIDE];

    int tid  = threadIdx.x;
    int wid  = tid >> 5;
    int lane = tid & 31;
    int wm = wid >> 2;   // 0..1  (64 rows each)
    int wn = wid & 3;    // 0..3  (32 cols each)
    int m0 = blockIdx.x * 128;

    int arow[2], aseg[2], brow[2], bseg[2];
    #pragma unroll
    for (int i = 0; i < 2; i++) {
        int chunk = tid + i * 256;
        arow[i] = chunk >> 2;  aseg[i] = chunk & 3;
        brow[i] = chunk >> 4;  bseg[i] = chunk & 15;
    }

    float c[4][4][4];
    #pragma unroll
    for (int i = 0; i < 4; i++)
        #pragma unroll
        for (int j = 0; j < 4; j++)
            #pragma unroll
            for (int t = 0; t < 4; t++) c[i][j][t] = 0.0f;

    int lrow  = lane & 15;
    int lcolh = (lane >> 4) * 8;

    auto issue = [&](int kt) {
        int st = kt & 1;
        #pragma unroll
        for (int i = 0; i < 2; i++) {
            int rg = m0 + arow[i];
            bool ok = (rg < nq);
            const __half* src = g_weighted +
                (size_t)(ok ? rg : 0) * KC + kt * 32 + aseg[i] * 8;
            cp16(smem_u32(&As[st][arow[i] * AS_STRIDE + aseg[i] * 8]), src, ok);
        }
        #pragma unroll
        for (int i = 0; i < 2; i++) {
            const __half* src = g_wts + (kt * 32 + brow[i]) * COUT + bseg[i] * 8;
            cp16(smem_u32(&Bs[st][brow[i] * BS_STRIDE + bseg[i] * 8]), src, true);
        }
    };

    issue(0);
    asm volatile("cp.async.commit_group;" ::: "memory");

    for (int kt = 0; kt < NKT; kt++) {
        if (kt + 1 < NKT) issue(kt + 1);
        asm volatile("cp.async.commit_group;" ::: "memory");
        asm volatile("cp.async.wait_group 1;" ::: "memory");
        __syncthreads();

        int st = kt & 1;
        #pragma unroll
        for (int ks = 0; ks < 2; ks++) {
            uint32_t a[4][4], b[4][2];
            #pragma unroll
            for (int im = 0; im < 4; im++) {
                uint32_t addr = smem_u32(
                    &As[st][(wm * 64 + im * 16 + lrow) * AS_STRIDE + ks * 16 + lcolh]);
                ldm_x4(a[im][0], a[im][1], a[im][2], a[im][3], addr);
            }
            #pragma unroll
            for (int ip = 0; ip < 2; ip++) {
                uint32_t addr = smem_u32(
                    &Bs[st][(ks * 16 + lrow) * BS_STRIDE + wn * 32 + ip * 16 + lcolh]);
                uint32_t r0, r1, r2, r3;
                ldm_x4_t(r0, r1, r2, r3, addr);
                b[ip * 2 + 0][0] = r0; b[ip * 2 + 0][1] = r1;
                b[ip * 2 + 1][0] = r2; b[ip * 2 + 1][1] = r3;
            }
            #pragma unroll
            for (int im = 0; im < 4; im++)
                #pragma unroll
                for (int in = 0; in < 4; in++)
                    mma16816(c[im][in][0], c[im][in][1], c[im][in][2], c[im][in][3],
                             a[im][0], a[im][1], a[im][2], a[im][3],
                             b[in][0], b[in][1]);
        }
        __syncthreads();
    }

    // Epilogue
    int gid = lane >> 2, tig = lane & 3;
    #pragma unroll
    for (int im = 0; im < 4; im++) {
        #pragma unroll
        for (int in = 0; in < 4; in++) {
            int row = m0 + wm * 64 + im * 16 + gid;
            int col = wn * 32 + in * 8 + tig * 2;
            if (row < nq) {
                float2 v0 = make_float2(c[im][in][0], c[im][in][1]);
                *(float2*)(out + (size_t)row * COUT + col) = v0;
            }
            if (row + 8 < nq) {
                float2 v1 = make_float2(c[im][in][2], c[im][in][3]);
                *(float2*)(out + (size_t)(row + 8) * COUT + col) = v1;
            }
        }
    }
}

// ---------------------------------------------------------------------------
extern "C" void kernel_launch(void* const* d_in, const int* in_sizes, int n_in,
                              void* d_out, int out_size) {
    const float* qp = (const float*)d_in[0];   // query_points   [N,3]
    const float* sp = (const float*)d_in[1];   // support_points [M,3]
    const int*   ni = (const int*)  d_in[2];   // neighbors_idx  [N,32]
    const float* ft = (const float*)d_in[3];   // features       [M,64]
    const float* kp = (const float*)d_in[4];   // kernel_points  [15,3]
    const float* wt = (const float*)d_in[5];   // wts            [15,64,128]
    float* out = (float*)d_out;

    int nq = in_sizes[0] / 3;
    int m  = in_sizes[1] / 3;

    prep_kernel<<<(KC * COUT + 255) / 256, 256>>>(wt, sp, m);
    weight_kernel<<<(nq + 15) / 16, 128>>>(qp, ni, ft, kp, nq);
    gemm_kernel<<<(nq + 127) / 128, 256>>>(out, nq);
}

// round 10
// speedup vs baseline: 1.0543x; 1.0543x over previous
#include <cuda_runtime.h>
#include <cuda_fp16.h>
#include <stdint.h>

// Problem constants (fixed by setup_inputs)
#define NQ   100000
#define HN   32      // neighbors per query
#define KP   15      // kernel points
#define CIN  64
#define COUT 128
#define KC   (KP * CIN)   // 960
#define MAXM 100000  // support points (fixed by setup_inputs)
#define KP_EXT 1.2f
#define KP_EXT2 (KP_EXT * KP_EXT)   // 1.44

// Scratch (device globals: allocation-free)
__device__ __half  g_weighted[(size_t)NQ * KC];  // [N][K*Cin] fp16, ~192 MB
__device__ __half  g_wts[KC * COUT];             // [K*Cin][Cout] fp16
__device__ float4  g_spts4[MAXM];                // padded support points, 1.6 MB
__device__ __half2 g_feats2[(size_t)MAXM * 32];  // fp16 features, 12.8 MB (L2-resident)

__device__ __forceinline__ uint32_t smem_u32(const void* p) {
    uint32_t a;
    asm("{ .reg .u64 t; cvta.to.shared.u64 t, %1; cvt.u32.u64 %0, t; }"
        : "=r"(a) : "l"(p));
    return a;
}
__device__ __forceinline__ float sqrt_approx(float x) {
    float r;
    asm("sqrt.approx.f32 %0, %1;" : "=f"(r) : "f"(x));
    return r;
}

// ---------------------------------------------------------------------------
// Kernel 0: prep — wts fp32->fp16, float4 support points, half2 features.
// ---------------------------------------------------------------------------
__global__ void prep_kernel(const float* __restrict__ wts,
                            const float* __restrict__ spts,
                            const float* __restrict__ feats,
                            int m) {
    int i = blockIdx.x * blockDim.x + threadIdx.x;
    if (i < KC * COUT) g_wts[i] = __float2half(wts[i]);
    if (i < m)
        g_spts4[i] = make_float4(spts[3 * i + 0], spts[3 * i + 1],
                                 spts[3 * i + 2], 0.0f);
    if (i < m * 32) {
        const float2* f2 = (const float2*)feats;
        float2 f = f2[i];
        g_feats2[i] = __floats2half2_rn(f.x, f.y);
    }
}

// ---------------------------------------------------------------------------
// Kernel 1: weights + sparse weighted feature aggregation.
// vs round 9: unconditional MUFU sqrt.approx (kills the ~12-instr IEEE sqrt
// sequence executed under a 92%-taken divergent branch), half2 feature gather
// (1 L1 wavefront per row instead of 2, no cvt), folded -2 constants.
// ---------------------------------------------------------------------------
__global__ void __launch_bounds__(128, 12) weight_kernel(
    const float* __restrict__ qpts,
    const int*   __restrict__ nidx,
    const float* __restrict__ kpts,
    int nq)
{
    __shared__ __half2 Fs[4][HN * 32];  // [warp][h][c-pair]  4*4KB = 16KB
    __shared__ float4 skp[KP];          // (-2kx, -2ky, -2kz, |kp|^2)

    int tid = threadIdx.x;
    if (tid < KP) {
        float kx = kpts[3 * tid + 0];
        float ky = kpts[3 * tid + 1];
        float kz = kpts[3 * tid + 2];
        skp[tid] = make_float4(-2.0f * kx, -2.0f * ky, -2.0f * kz,
                               kx * kx + ky * ky + kz * kz);
    }
    __syncthreads();

    int warp = tid >> 5;
    int lane = tid & 31;
    const float inv_ext = 1.0f / KP_EXT;
    int qbase = blockIdx.x * 16 + warp * 4;

    __half2* FsW = Fs[warp];
    __half2* outp = (__half2*)g_weighted;

    #pragma unroll 1
    for (int qi = 0; qi < 4; qi++) {
        int q = qbase + qi;
        if (q >= nq) return;   // warp-uniform

        // ---- weights: lane owns neighbor h = lane ----
        int idx = nidx[q * HN + lane];
        float4 sp = g_spts4[idx];                  // single LDG.128
        float qx = qpts[q * 3 + 0];
        float qy = qpts[q * 3 + 1];
        float qz = qpts[q * 3 + 2];
        float px = sp.x - qx;
        float py = sp.y - qy;
        float pz = sp.z - qz;
        float pp = px * px + py * py + pz * pz;

        uint32_t w2[KP];                           // half2(w, w)
        unsigned m[KP];
        unsigned active_h = 0;
        #pragma unroll
        for (int k = 0; k < KP; k++) {
            float4 kv = skp[k];
            // d2 = |p|^2 + |kp|^2 - 2 p.kp  (constants pre-scaled by -2)
            float d2 = fmaf(px, kv.x, fmaf(py, kv.y, fmaf(pz, kv.z, pp + kv.w)));
            float s  = sqrt_approx(fmaxf(d2, 0.0f));     // 1 MUFU op
            float wv = fmaxf(fmaf(-s, inv_ext, 1.0f), 0.0f);
            __half2 wh = __floats2half2_rn(wv, wv);
            w2[k] = *reinterpret_cast<uint32_t*>(&wh);
            m[k] = __ballot_sync(0xffffffffu, wv > 0.0f);
            active_h |= m[k];
        }

        // ---- Phase A: stage active neighbor features (half2, 4B/lane) ----
        __syncwarp();
        unsigned aa = active_h;
        while (aa) {
            int h = __ffs(aa) - 1;
            aa &= aa - 1;
            int ih = __shfl_sync(0xffffffffu, idx, h);
            FsW[h * 32 + lane] = g_feats2[(size_t)ih * 32 + lane];
        }
        __syncwarp();

        // ---- Phase B: sparse per-k accumulation (fp16 HFMA2) ----
        #pragma unroll
        for (int k = 0; k < KP; k++) {
            __half2 acc = __floats2half2_rn(0.0f, 0.0f);
            unsigned mm = m[k];
            while (mm) {
                int h = __ffs(mm) - 1;
                mm &= mm - 1;
                uint32_t wk = __shfl_sync(0xffffffffu, w2[k], h);
                acc = __hfma2(*reinterpret_cast<__half2*>(&wk),
                              FsW[h * 32 + lane], acc);
            }
            outp[(size_t)q * (KC / 2) + k * 32 + lane] = acc;
        }
    }
}

// ---------------------------------------------------------------------------
// Kernel 2: GEMM out[N][128] = weighted[N][960] (f16) x wts[960][128] (f16)
// 128x128 tile, 8 warps (64x32 each), m16n8k16 HMMA, 2-stage cp.async pipeline.
// (At the legacy-HMMA throughput floor ~90us; left unchanged.)
// ---------------------------------------------------------------------------
__device__ __forceinline__ void ldm_x4(uint32_t& r0, uint32_t& r1,
                                       uint32_t& r2, uint32_t& r3,
                                       uint32_t addr) {
    asm volatile("ldmatrix.sync.aligned.m8n8.x4.shared.b16 {%0,%1,%2,%3}, [%4];"
                 : "=r"(r0), "=r"(r1), "=r"(r2), "=r"(r3) : "r"(addr));
}
__device__ __forceinline__ void ldm_x4_t(uint32_t& r0, uint32_t& r1,
                                         uint32_t& r2, uint32_t& r3,
                                         uint32_t addr) {
    asm volatile("ldmatrix.sync.aligned.m8n8.x4.trans.shared.b16 {%0,%1,%2,%3}, [%4];"
                 : "=r"(r0), "=r"(r1), "=r"(r2), "=r"(r3) : "r"(addr));
}
__device__ __forceinline__ void mma16816(float& c0, float& c1, float& c2, float& c3,
                                         uint32_t a0, uint32_t a1, uint32_t a2, uint32_t a3,
                                         uint32_t b0, uint32_t b1) {
    asm volatile(
        "mma.sync.aligned.m16n8k16.row.col.f32.f16.f16.f32 "
        "{%0,%1,%2,%3}, {%4,%5,%6,%7}, {%8,%9}, {%0,%1,%2,%3};"
        : "+f"(c0), "+f"(c1), "+f"(c2), "+f"(c3)
        : "r"(a0), "r"(a1), "r"(a2), "r"(a3), "r"(b0), "r"(b1));
}
__device__ __forceinline__ void cp16(uint32_t dst, const void* src, bool pred) {
    int sz = pred ? 16 : 0;
    asm volatile("cp.async.cg.shared.global [%0], [%1], 16, %2;"
                 :: "r"(dst), "l"(src), "r"(sz) : "memory");
}

#define AS_STRIDE 48    // halves per A row (32 data + 16 pad)
#define BS_STRIDE 136   // halves per B row (128 data + 8 pad)
#define NKT (KC / 32)   // 30 k-iterations

__global__ void __launch_bounds__(256) gemm_kernel(float* __restrict__ out, int nq) {
    __shared__ __half As[2][128 * AS_STRIDE];
    __shared__ __half Bs[2][32 * BS_STRIDE];

    int tid  = threadIdx.x;
    int wid  = tid >> 5;
    int lane = tid & 31;
    int wm = wid >> 2;   // 0..1  (64 rows each)
    int wn = wid & 3;    // 0..3  (32 cols each)
    int m0 = blockIdx.x * 128;

    int arow[2], aseg[2], brow[2], bseg[2];
    #pragma unroll
    for (int i = 0; i < 2; i++) {
        int chunk = tid + i * 256;
        arow[i] = chunk >> 2;  aseg[i] = chunk & 3;
        brow[i] = chunk >> 4;  bseg[i] = chunk & 15;
    }

    float c[4][4][4];
    #pragma unroll
    for (int i = 0; i < 4; i++)
        #pragma unroll
        for (int j = 0; j < 4; j++)
            #pragma unroll
            for (int t = 0; t < 4; t++) c[i][j][t] = 0.0f;

    int lrow  = lane & 15;
    int lcolh = (lane >> 4) * 8;

    auto issue = [&](int kt) {
        int st = kt & 1;
        #pragma unroll
        for (int i = 0; i < 2; i++) {
            int rg = m0 + arow[i];
            bool ok = (rg < nq);
            const __half* src = g_weighted +
                (size_t)(ok ? rg : 0) * KC + kt * 32 + aseg[i] * 8;
            cp16(smem_u32(&As[st][arow[i] * AS_STRIDE + aseg[i] * 8]), src, ok);
        }
        #pragma unroll
        for (int i = 0; i < 2; i++) {
            const __half* src = g_wts + (kt * 32 + brow[i]) * COUT + bseg[i] * 8;
            cp16(smem_u32(&Bs[st][brow[i] * BS_STRIDE + bseg[i] * 8]), src, true);
        }
    };

    issue(0);
    asm volatile("cp.async.commit_group;" ::: "memory");

    for (int kt = 0; kt < NKT; kt++) {
        if (kt + 1 < NKT) issue(kt + 1);
        asm volatile("cp.async.commit_group;" ::: "memory");
        asm volatile("cp.async.wait_group 1;" ::: "memory");
        __syncthreads();

        int st = kt & 1;
        #pragma unroll
        for (int ks = 0; ks < 2; ks++) {
            uint32_t a[4][4], b[4][2];
            #pragma unroll
            for (int im = 0; im < 4; im++) {
                uint32_t addr = smem_u32(
                    &As[st][(wm * 64 + im * 16 + lrow) * AS_STRIDE + ks * 16 + lcolh]);
                ldm_x4(a[im][0], a[im][1], a[im][2], a[im][3], addr);
            }
            #pragma unroll
            for (int ip = 0; ip < 2; ip++) {
                uint32_t addr = smem_u32(
                    &Bs[st][(ks * 16 + lrow) * BS_STRIDE + wn * 32 + ip * 16 + lcolh]);
                uint32_t r0, r1, r2, r3;
                ldm_x4_t(r0, r1, r2, r3, addr);
                b[ip * 2 + 0][0] = r0; b[ip * 2 + 0][1] = r1;
                b[ip * 2 + 1][0] = r2; b[ip * 2 + 1][1] = r3;
            }
            #pragma unroll
            for (int im = 0; im < 4; im++)
                #pragma unroll
                for (int in = 0; in < 4; in++)
                    mma16816(c[im][in][0], c[im][in][1], c[im][in][2], c[im][in][3],
                             a[im][0], a[im][1], a[im][2], a[im][3],
                             b[in][0], b[in][1]);
        }
        __syncthreads();
    }

    // Epilogue
    int gid = lane >> 2, tig = lane & 3;
    #pragma unroll
    for (int im = 0; im < 4; im++) {
        #pragma unroll
        for (int in = 0; in < 4; in++) {
            int row = m0 + wm * 64 + im * 16 + gid;
            int col = wn * 32 + in * 8 + tig * 2;
            if (row < nq) {
                float2 v0 = make_float2(c[im][in][0], c[im][in][1]);
                *(float2*)(out + (size_t)row * COUT + col) = v0;
            }
            if (row + 8 < nq) {
                float2 v1 = make_float2(c[im][in][2], c[im][in][3]);
                *(float2*)(out + (size_t)(row + 8) * COUT + col) = v1;
            }
        }
    }
}

// ---------------------------------------------------------------------------
extern "C" void kernel_launch(void* const* d_in, const int* in_sizes, int n_in,
                              void* d_out, int out_size) {
    const float* qp = (const float*)d_in[0];   // query_points   [N,3]
    const float* sp = (const float*)d_in[1];   // support_points [M,3]
    const int*   ni = (const int*)  d_in[2];   // neighbors_idx  [N,32]
    const float* ft = (const float*)d_in[3];   // features       [M,64]
    const float* kp = (const float*)d_in[4];   // kernel_points  [15,3]
    const float* wt = (const float*)d_in[5];   // wts            [15,64,128]
    float* out = (float*)d_out;

    int nq = in_sizes[0] / 3;
    int m  = in_sizes[1] / 3;

    int prep_elems = m * 32;                    // features dominate
    if (prep_elems < KC * COUT) prep_elems = KC * COUT;
    prep_kernel<<<(prep_elems + 255) / 256, 256>>>(wt, sp, ft, m);
    weight_kernel<<<(nq + 15) / 16, 128>>>(qp, ni, kp, nq);
    gemm_kernel<<<(nq + 127) / 128, 256>>>(out, nq);
}

// round 14
// speedup vs baseline: 1.1244x; 1.0665x over previous
#include <cuda_runtime.h>
#include <cuda_fp16.h>
#include <stdint.h>

// Problem constants (fixed by setup_inputs)
#define NQ   100000
#define HN   32      // neighbors per query
#define KP   15      // kernel points
#define CIN  64
#define COUT 128
#define KC   (KP * CIN)   // 960
#define MAXM 100000  // support points (fixed by setup_inputs)
#define KP_EXT 1.2f
#define KP_EXT2 (KP_EXT * KP_EXT)   // 1.44

// Scratch (device globals: allocation-free)
__device__ __half  g_weighted[(size_t)NQ * KC];  // [N][K*Cin] fp16, ~192 MB
__device__ __half  g_wts[KC * COUT];             // [K*Cin][Cout] fp16
__device__ float4  g_spts4[MAXM];                // padded support points, 1.6 MB
__device__ float4  g_qpts4[NQ];                  // padded query points, 1.6 MB
__device__ __half2 g_feats2[(size_t)MAXM * 32];  // fp16 features, 12.8 MB (L2-resident)

__device__ __forceinline__ uint32_t smem_u32(const void* p) {
    uint32_t a;
    asm("{ .reg .u64 t; cvta.to.shared.u64 t, %1; cvt.u32.u64 %0, t; }"
        : "=r"(a) : "l"(p));
    return a;
}
__device__ __forceinline__ float sqrt_approx(float x) {
    float r;
    asm("sqrt.approx.f32 %0, %1;" : "=f"(r) : "f"(x));
    return r;
}

// ---------------------------------------------------------------------------
// Kernel 0: prep — wts fp32->fp16, float4 points, half2 features (vectorized).
// ---------------------------------------------------------------------------
__global__ void prep_kernel(const float* __restrict__ wts,
                            const float* __restrict__ spts,
                            const float* __restrict__ qpts,
                            const float* __restrict__ feats,
                            int m, int nq) {
    int i = blockIdx.x * blockDim.x + threadIdx.x;
    if (i < KC * COUT) g_wts[i] = __float2half(wts[i]);
    if (i < m)
        g_spts4[i] = make_float4(spts[3 * i + 0], spts[3 * i + 1],
                                 spts[3 * i + 2], 0.0f);
    if (i < nq)
        g_qpts4[i] = make_float4(qpts[3 * i + 0], qpts[3 * i + 1],
                                 qpts[3 * i + 2], 0.0f);
    if (i < m * 16) {                         // feats: m*64 floats = m*16 float4
        float4 f = ((const float4*)feats)[i];
        __half2* dst = (__half2*)g_feats2;
        dst[2 * i + 0] = __floats2half2_rn(f.x, f.y);
        dst[2 * i + 1] = __floats2half2_rn(f.z, f.w);
    }
}

// ---------------------------------------------------------------------------
// Kernel 1: weights + sparse weighted feature aggregation.
// 13 blocks/SM (52 warps theoretical), float4 point loads.
// ---------------------------------------------------------------------------
__global__ void __launch_bounds__(128, 13) weight_kernel(
    const int*   __restrict__ nidx,
    const float* __restrict__ kpts,
    int nq)
{
    __shared__ __half2 Fs[4][HN * 32];  // [warp][h][c-pair]  4*4KB = 16KB
    __shared__ float4 skp[KP];          // (-2kx, -2ky, -2kz, |kp|^2)

    int tid = threadIdx.x;
    if (tid < KP) {
        float kx = kpts[3 * tid + 0];
        float ky = kpts[3 * tid + 1];
        float kz = kpts[3 * tid + 2];
        skp[tid] = make_float4(-2.0f * kx, -2.0f * ky, -2.0f * kz,
                               kx * kx + ky * ky + kz * kz);
    }
    __syncthreads();

    int warp = tid >> 5;
    int lane = tid & 31;
    const float inv_ext = 1.0f / KP_EXT;
    int qbase = blockIdx.x * 16 + warp * 4;

    __half2* FsW = Fs[warp];
    __half2* outp = (__half2*)g_weighted;

    #pragma unroll 1
    for (int qi = 0; qi < 4; qi++) {
        int q = qbase + qi;
        if (q >= nq) return;   // warp-uniform

        // ---- weights: lane owns neighbor h = lane ----
        int idx = nidx[q * HN + lane];
        float4 sp = g_spts4[idx];                  // single LDG.128
        float4 qp = g_qpts4[q];                    // single LDG.128 (broadcast)
        float px = sp.x - qp.x;
        float py = sp.y - qp.y;
        float pz = sp.z - qp.z;
        float pp = px * px + py * py + pz * pz;

        uint32_t w2[KP];                           // half2(w, w)
        unsigned m[KP];
        unsigned active_h = 0;
        #pragma unroll
        for (int k = 0; k < KP; k++) {
            float4 kv = skp[k];
            // d2 = |p|^2 + |kp|^2 - 2 p.kp  (constants pre-scaled by -2)
            float d2 = fmaf(px, kv.x, fmaf(py, kv.y, fmaf(pz, kv.z, pp + kv.w)));
            float s  = sqrt_approx(fmaxf(d2, 0.0f));     // 1 MUFU op
            float wv = fmaxf(fmaf(-s, inv_ext, 1.0f), 0.0f);
            __half2 wh = __floats2half2_rn(wv, wv);
            w2[k] = *reinterpret_cast<uint32_t*>(&wh);
            m[k] = __ballot_sync(0xffffffffu, wv > 0.0f);
            active_h |= m[k];
        }

        // ---- Phase A: stage active neighbor features (half2, 4B/lane) ----
        __syncwarp();
        unsigned aa = active_h;
        while (aa) {
            int h = __ffs(aa) - 1;
            aa &= aa - 1;
            int ih = __shfl_sync(0xffffffffu, idx, h);
            FsW[h * 32 + lane] = g_feats2[(size_t)ih * 32 + lane];
        }
        __syncwarp();

        // ---- Phase B: sparse per-k accumulation (fp16 HFMA2) ----
        #pragma unroll
        for (int k = 0; k < KP; k++) {
            __half2 acc = __floats2half2_rn(0.0f, 0.0f);
            unsigned mm = m[k];
            while (mm) {
                int h = __ffs(mm) - 1;
                mm &= mm - 1;
                uint32_t wk = __shfl_sync(0xffffffffu, w2[k], h);
                acc = __hfma2(*reinterpret_cast<__half2*>(&wk),
                              FsW[h * 32 + lane], acc);
            }
            outp[(size_t)q * (KC / 2) + k * 32 + lane] = acc;
        }
    }
}

// ---------------------------------------------------------------------------
// Kernel 2: GEMM out[N][128] = weighted[N][960] (f16) x wts[960][128] (f16)
// 128x128 tile, 8 warps (64x32 each), m16n8k16 HMMA.
// Asymmetric pipeline in STATIC smem: 3 A-stages (DRAM-critical operand,
// prefetch distance 2) + 2 B-stages (L2-resident wts).
// 3*128*40*2 + 2*32*136*2 = 30720 + 17408 = 48128 <= 49152 (0xc000). Fits.
// All stage row strides are multiples of 16B (A: 80B, B: 272B) — cp.async-legal.
// ---------------------------------------------------------------------------
__device__ __forceinline__ void ldm_x4(uint32_t& r0, uint32_t& r1,
                                       uint32_t& r2, uint32_t& r3,
                                       uint32_t addr) {
    asm volatile("ldmatrix.sync.aligned.m8n8.x4.shared.b16 {%0,%1,%2,%3}, [%4];"
                 : "=r"(r0), "=r"(r1), "=r"(r2), "=r"(r3) : "r"(addr));
}
__device__ __forceinline__ void ldm_x4_t(uint32_t& r0, uint32_t& r1,
                                         uint32_t& r2, uint32_t& r3,
                                         uint32_t addr) {
    asm volatile("ldmatrix.sync.aligned.m8n8.x4.trans.shared.b16 {%0,%1,%2,%3}, [%4];"
                 : "=r"(r0), "=r"(r1), "=r"(r2), "=r"(r3) : "r"(addr));
}
__device__ __forceinline__ void mma16816(float& c0, float& c1, float& c2, float& c3,
                                         uint32_t a0, uint32_t a1, uint32_t a2, uint32_t a3,
                                         uint32_t b0, uint32_t b1) {
    asm volatile(
        "mma.sync.aligned.m16n8k16.row.col.f32.f16.f16.f32 "
        "{%0,%1,%2,%3}, {%4,%5,%6,%7}, {%8,%9}, {%0,%1,%2,%3};"
        : "+f"(c0), "+f"(c1), "+f"(c2), "+f"(c3)
        : "r"(a0), "r"(a1), "r"(a2), "r"(a3), "r"(b0), "r"(b1));
}
__device__ __forceinline__ void cp16(uint32_t dst, const void* src, bool pred) {
    int sz = pred ? 16 : 0;
    asm volatile("cp.async.cg.shared.global [%0], [%1], 16, %2;"
                 :: "r"(dst), "l"(src), "r"(sz) : "memory");
}

#define AS_STRIDE 40    // halves per A row (80 B, 16B-aligned rows)
#define BS_STRIDE 136   // halves per B row (272 B, 16B-aligned rows)
#define NKT (KC / 32)   // 30 k-iterations

__global__ void __launch_bounds__(256) gemm_kernel(float* __restrict__ out, int nq) {
    __shared__ __half As[3][128 * AS_STRIDE];   // 30 KB
    __shared__ __half Bs[2][32 * BS_STRIDE];    // 17 KB

    int tid  = threadIdx.x;
    int wid  = tid >> 5;
    int lane = tid & 31;
    int wm = wid >> 2;   // 0..1  (64 rows each)
    int wn = wid & 3;    // 0..3  (32 cols each)
    int m0 = blockIdx.x * 128;

    int arow[2], aseg[2], brow[2], bseg[2];
    #pragma unroll
    for (int i = 0; i < 2; i++) {
        int chunk = tid + i * 256;
        arow[i] = chunk >> 2;  aseg[i] = chunk & 3;
        brow[i] = chunk >> 4;  bseg[i] = chunk & 15;
    }

    float c[4][4][4];
    #pragma unroll
    for (int i = 0; i < 4; i++)
        #pragma unroll
        for (int j = 0; j < 4; j++)
            #pragma unroll
            for (int t = 0; t < 4; t++) c[i][j][t] = 0.0f;

    int lrow  = lane & 15;
    int lcolh = (lane >> 4) * 8;

    auto issue = [&](int kt) {
        if (kt < NKT) {
            __half* A = As[kt % 3];
            __half* B = Bs[kt % 2];
            #pragma unroll
            for (int i = 0; i < 2; i++) {
                int rg = m0 + arow[i];
                bool ok = (rg < nq);
                const __half* src = g_weighted +
                    (size_t)(ok ? rg : 0) * KC + kt * 32 + aseg[i] * 8;
                cp16(smem_u32(A + arow[i] * AS_STRIDE + aseg[i] * 8), src, ok);
            }
            #pragma unroll
            for (int i = 0; i < 2; i++) {
                const __half* src = g_wts + (kt * 32 + brow[i]) * COUT + bseg[i] * 8;
                cp16(smem_u32(B + brow[i] * BS_STRIDE + bseg[i] * 8), src, true);
            }
        }
        asm volatile("cp.async.commit_group;" ::: "memory");  // one group per call
    };

    issue(0);
    issue(1);

    for (int kt = 0; kt < NKT; kt++) {
        asm volatile("cp.async.wait_group 1;" ::: "memory");  // group kt complete
        __syncthreads();

        __half* A = As[kt % 3];
        __half* B = Bs[kt % 2];
        #pragma unroll
        for (int ks = 0; ks < 2; ks++) {
            uint32_t a[4][4], b[4][2];
            #pragma unroll
            for (int im = 0; im < 4; im++) {
                uint32_t addr = smem_u32(
                    A + (wm * 64 + im * 16 + lrow) * AS_STRIDE + ks * 16 + lcolh);
                ldm_x4(a[im][0], a[im][1], a[im][2], a[im][3], addr);
            }
            #pragma unroll
            for (int ip = 0; ip < 2; ip++) {
                uint32_t addr = smem_u32(
                    B + (ks * 16 + lrow) * BS_STRIDE + wn * 32 + ip * 16 + lcolh);
                uint32_t r0, r1, r2, r3;
                ldm_x4_t(r0, r1, r2, r3, addr);
                b[ip * 2 + 0][0] = r0; b[ip * 2 + 0][1] = r1;
                b[ip * 2 + 1][0] = r2; b[ip * 2 + 1][1] = r3;
            }
            #pragma unroll
            for (int im = 0; im < 4; im++)
                #pragma unroll
                for (int in = 0; in < 4; in++)
                    mma16816(c[im][in][0], c[im][in][1], c[im][in][2], c[im][in][3],
                             a[im][0], a[im][1], a[im][2], a[im][3],
                             b[in][0], b[in][1]);
        }
        __syncthreads();   // all warps done reading A[kt%3], B[kt%2]
        issue(kt + 2);     // writes A[(kt-1)%3] (idle) and B[kt%2] (just fenced)
    }

    // Epilogue
    int gid = lane >> 2, tig = lane & 3;
    #pragma unroll
    for (int im = 0; im < 4; im++) {
        #pragma unroll
        for (int in = 0; in < 4; in++) {
            int row = m0 + wm * 64 + im * 16 + gid;
            int col = wn * 32 + in * 8 + tig * 2;
            if (row < nq) {
                float2 v0 = make_float2(c[im][in][0], c[im][in][1]);
                *(float2*)(out + (size_t)row * COUT + col) = v0;
            }
            if (row + 8 < nq) {
                float2 v1 = make_float2(c[im][in][2], c[im][in][3]);
                *(float2*)(out + (size_t)(row + 8) * COUT + col) = v1;
            }
        }
    }
}

// ---------------------------------------------------------------------------
extern "C" void kernel_launch(void* const* d_in, const int* in_sizes, int n_in,
                              void* d_out, int out_size) {
    const float* qp = (const float*)d_in[0];   // query_points   [N,3]
    const float* sp = (const float*)d_in[1];   // support_points [M,3]
    const int*   ni = (const int*)  d_in[2];   // neighbors_idx  [N,32]
    const float* ft = (const float*)d_in[3];   // features       [M,64]
    const float* kp = (const float*)d_in[4];   // kernel_points  [15,3]
    const float* wt = (const float*)d_in[5];   // wts            [15,64,128]
    float* out = (float*)d_out;

    int nq = in_sizes[0] / 3;
    int m  = in_sizes[1] / 3;

    int prep_elems = m * 16;                    // features dominate (float4 units)
    if (prep_elems < KC * COUT) prep_elems = KC * COUT;
    if (prep_elems < nq) prep_elems = nq;
    prep_kernel<<<(prep_elems + 255) / 256, 256>>>(wt, sp, qp, ft, m, nq);
    weight_kernel<<<(nq + 15) / 16, 128>>>(ni, kp, nq);
    gemm_kernel<<<(nq + 127) / 128, 256>>>(out, nq);
}

// round 15
// speedup vs baseline: 1.2524x; 1.1138x over previous
#include <cuda_runtime.h>
#include <cuda_fp16.h>
#include <stdint.h>

// Problem constants (fixed by setup_inputs)
#define NQ   100000
#define HN   32      // neighbors per query
#define KP   15      // kernel points
#define CIN  64
#define COUT 128
#define KC   (KP * CIN)   // 960
#define MAXM 100000  // support points (fixed by setup_inputs)
#define KP_EXT 1.2f
#define KP_EXT2 (KP_EXT * KP_EXT)   // 1.44

// Scratch (device globals: allocation-free)
__device__ __half  g_weighted[(size_t)NQ * KC];  // [N][K*Cin] fp16, ~192 MB
__device__ __half  g_wts[KC * COUT];             // [K*Cin][Cout] fp16
__device__ float4  g_spts4[MAXM];                // padded support points, 1.6 MB
__device__ float4  g_qpts4[NQ];                  // padded query points, 1.6 MB
__device__ __half2 g_feats2[(size_t)MAXM * 32];  // fp16 features, 12.8 MB (L2-resident)

__device__ __forceinline__ uint32_t smem_u32(const void* p) {
    uint32_t a;
    asm("{ .reg .u64 t; cvta.to.shared.u64 t, %1; cvt.u32.u64 %0, t; }"
        : "=r"(a) : "l"(p));
    return a;
}
__device__ __forceinline__ float sqrt_approx(float x) {
    float r;
    asm("sqrt.approx.f32 %0, %1;" : "=f"(r) : "f"(x));
    return r;
}

// ---------------------------------------------------------------------------
// Kernel 0: prep — wts fp32->fp16, float4 points, half2 features (vectorized).
// ---------------------------------------------------------------------------
__global__ void prep_kernel(const float* __restrict__ wts,
                            const float* __restrict__ spts,
                            const float* __restrict__ qpts,
                            const float* __restrict__ feats,
                            int m, int nq) {
    int i = blockIdx.x * blockDim.x + threadIdx.x;
    if (i < KC * COUT) g_wts[i] = __float2half(wts[i]);
    if (i < m)
        g_spts4[i] = make_float4(spts[3 * i + 0], spts[3 * i + 1],
                                 spts[3 * i + 2], 0.0f);
    if (i < nq)
        g_qpts4[i] = make_float4(qpts[3 * i + 0], qpts[3 * i + 1],
                                 qpts[3 * i + 2], 0.0f);
    if (i < m * 16) {                         // feats: m*64 floats = m*16 float4
        float4 f = ((const float4*)feats)[i];
        __half2* dst = (__half2*)g_feats2;
        dst[2 * i + 0] = __floats2half2_rn(f.x, f.y);
        dst[2 * i + 1] = __floats2half2_rn(f.z, f.w);
    }
}

// ---------------------------------------------------------------------------
// Kernel 1: weights + weighted aggregation, SINGLE-PASS k-loop.
// vs round 14: the w2[15]/m[15] register arrays (30 regs of live state that
// forced local-memory spills under the 13-block reg bound) are gone:
//  - stage ALL 32 neighbor feature rows unconditionally (no active mask),
//  - then one fused loop per k: compute w -> ballot -> bit-walk -> store,
//    with w2/mm as iteration-local scalars.
// ---------------------------------------------------------------------------
__global__ void __launch_bounds__(128, 13) weight_kernel(
    const int*   __restrict__ nidx,
    const float* __restrict__ kpts,
    int nq)
{
    __shared__ __half2 Fs[4][HN * 32];  // [warp][h][c-pair]  4*4KB = 16KB
    __shared__ float4 skp[KP];          // (-2kx, -2ky, -2kz, |kp|^2)

    int tid = threadIdx.x;
    if (tid < KP) {
        float kx = kpts[3 * tid + 0];
        float ky = kpts[3 * tid + 1];
        float kz = kpts[3 * tid + 2];
        skp[tid] = make_float4(-2.0f * kx, -2.0f * ky, -2.0f * kz,
                               kx * kx + ky * ky + kz * kz);
    }
    __syncthreads();

    int warp = tid >> 5;
    int lane = tid & 31;
    const float inv_ext = 1.0f / KP_EXT;
    int qbase = blockIdx.x * 16 + warp * 4;

    __half2* FsW = Fs[warp];
    __half2* outp = (__half2*)g_weighted;

    #pragma unroll 1
    for (int qi = 0; qi < 4; qi++) {
        int q = qbase + qi;
        if (q >= nq) return;   // warp-uniform

        // ---- geometry: lane owns neighbor h = lane ----
        int idx = nidx[q * HN + lane];
        float4 sp = g_spts4[idx];                  // single LDG.128
        float4 qp = g_qpts4[q];                    // single LDG.128 (broadcast)
        float px = sp.x - qp.x;
        float py = sp.y - qp.y;
        float pz = sp.z - qp.z;
        float pp = px * px + py * py + pz * pz;

        // ---- stage all 32 neighbor feature rows (MLP 32, no masks) ----
        __syncwarp();
        #pragma unroll
        for (int h = 0; h < HN; h++) {
            int ih = __shfl_sync(0xffffffffu, idx, h);
            FsW[h * 32 + lane] = g_feats2[(size_t)ih * 32 + lane];
        }
        __syncwarp();

        // ---- fused per-k: weight -> ballot -> sparse accumulate -> store ----
        size_t qb = (size_t)q * (KC / 2);
        #pragma unroll
        for (int k = 0; k < KP; k++) {
            float4 kv = skp[k];
            // d2 = |p|^2 + |kp|^2 - 2 p.kp  (constants pre-scaled by -2)
            float d2 = fmaf(px, kv.x, fmaf(py, kv.y, fmaf(pz, kv.z, pp + kv.w)));
            float s  = sqrt_approx(fmaxf(d2, 0.0f));     // 1 MUFU op
            float wv = fmaxf(fmaf(-s, inv_ext, 1.0f), 0.0f);
            __half2 wh = __floats2half2_rn(wv, wv);
            uint32_t w2 = *reinterpret_cast<uint32_t*>(&wh);
            unsigned mm = __ballot_sync(0xffffffffu, wv > 0.0f);

            __half2 acc = __floats2half2_rn(0.0f, 0.0f);
            while (mm) {
                int h = __ffs(mm) - 1;
                mm &= mm - 1;
                uint32_t wk = __shfl_sync(0xffffffffu, w2, h);
                acc = __hfma2(*reinterpret_cast<__half2*>(&wk),
                              FsW[h * 32 + lane], acc);
            }
            outp[qb + k * 32 + lane] = acc;
        }
    }
}

// ---------------------------------------------------------------------------
// Kernel 2: GEMM out[N][128] = weighted[N][960] (f16) x wts[960][128] (f16)
// 128x128 tile, 8 warps (64x32 each), m16n8k16 HMMA.
// Asymmetric static-smem pipeline: 3 A-stages + 2 B-stages (48128 B <= 49152).
// AT THE LEGACY-HMMA THROUGHPUT FLOOR (~85us) — frozen.
// ---------------------------------------------------------------------------
__device__ __forceinline__ void ldm_x4(uint32_t& r0, uint32_t& r1,
                                       uint32_t& r2, uint32_t& r3,
                                       uint32_t addr) {
    asm volatile("ldmatrix.sync.aligned.m8n8.x4.shared.b16 {%0,%1,%2,%3}, [%4];"
                 : "=r"(r0), "=r"(r1), "=r"(r2), "=r"(r3) : "r"(addr));
}
__device__ __forceinline__ void ldm_x4_t(uint32_t& r0, uint32_t& r1,
                                         uint32_t& r2, uint32_t& r3,
                                         uint32_t addr) {
    asm volatile("ldmatrix.sync.aligned.m8n8.x4.trans.shared.b16 {%0,%1,%2,%3}, [%4];"
                 : "=r"(r0), "=r"(r1), "=r"(r2), "=r"(r3) : "r"(addr));
}
__device__ __forceinline__ void mma16816(float& c0, float& c1, float& c2, float& c3,
                                         uint32_t a0, uint32_t a1, uint32_t a2, uint32_t a3,
                                         uint32_t b0, uint32_t b1) {
    asm volatile(
        "mma.sync.aligned.m16n8k16.row.col.f32.f16.f16.f32 "
        "{%0,%1,%2,%3}, {%4,%5,%6,%7}, {%8,%9}, {%0,%1,%2,%3};"
        : "+f"(c0), "+f"(c1), "+f"(c2), "+f"(c3)
        : "r"(a0), "r"(a1), "r"(a2), "r"(a3), "r"(b0), "r"(b1));
}
__device__ __forceinline__ void cp16(uint32_t dst, const void* src, bool pred) {
    int sz = pred ? 16 : 0;
    asm volatile("cp.async.cg.shared.global [%0], [%1], 16, %2;"
                 :: "r"(dst), "l"(src), "r"(sz) : "memory");
}

#define AS_STRIDE 40    // halves per A row (80 B, 16B-aligned rows)
#define BS_STRIDE 136   // halves per B row (272 B, 16B-aligned rows)
#define NKT (KC / 32)   // 30 k-iterations

__global__ void __launch_bounds__(256) gemm_kernel(float* __restrict__ out, int nq) {
    __shared__ __half As[3][128 * AS_STRIDE];   // 30 KB
    __shared__ __half Bs[2][32 * BS_STRIDE];    // 17 KB

    int tid  = threadIdx.x;
    int wid  = tid >> 5;
    int lane = tid & 31;
    int wm = wid >> 2;   // 0..1  (64 rows each)
    int wn = wid & 3;    // 0..3  (32 cols each)
    int m0 = blockIdx.x * 128;

    int arow[2], aseg[2], brow[2], bseg[2];
    #pragma unroll
    for (int i = 0; i < 2; i++) {
        int chunk = tid + i * 256;
        arow[i] = chunk >> 2;  aseg[i] = chunk & 3;
        brow[i] = chunk >> 4;  bseg[i] = chunk & 15;
    }

    float c[4][4][4];
    #pragma unroll
    for (int i = 0; i < 4; i++)
        #pragma unroll
        for (int j = 0; j < 4; j++)
            #pragma unroll
            for (int t = 0; t < 4; t++) c[i][j][t] = 0.0f;

    int lrow  = lane & 15;
    int lcolh = (lane >> 4) * 8;

    auto issue = [&](int kt) {
        if (kt < NKT) {
            __half* A = As[kt % 3];
            __half* B = Bs[kt % 2];
            #pragma unroll
            for (int i = 0; i < 2; i++) {
                int rg = m0 + arow[i];
                bool ok = (rg < nq);
                const __half* src = g_weighted +
                    (size_t)(ok ? rg : 0) * KC + kt * 32 + aseg[i] * 8;
                cp16(smem_u32(A + arow[i] * AS_STRIDE + aseg[i] * 8), src, ok);
            }
            #pragma unroll
            for (int i = 0; i < 2; i++) {
                const __half* src = g_wts + (kt * 32 + brow[i]) * COUT + bseg[i] * 8;
                cp16(smem_u32(B + brow[i] * BS_STRIDE + bseg[i] * 8), src, true);
            }
        }
        asm volatile("cp.async.commit_group;" ::: "memory");  // one group per call
    };

    issue(0);
    issue(1);

    for (int kt = 0; kt < NKT; kt++) {
        asm volatile("cp.async.wait_group 1;" ::: "memory");  // group kt complete
        __syncthreads();

        __half* A = As[kt % 3];
        __half* B = Bs[kt % 2];
        #pragma unroll
        for (int ks = 0; ks < 2; ks++) {
            uint32_t a[4][4], b[4][2];
            #pragma unroll
            for (int im = 0; im < 4; im++) {
                uint32_t addr = smem_u32(
                    A + (wm * 64 + im * 16 + lrow) * AS_STRIDE + ks * 16 + lcolh);
                ldm_x4(a[im][0], a[im][1], a[im][2], a[im][3], addr);
            }
            #pragma unroll
            for (int ip = 0; ip < 2; ip++) {
                uint32_t addr = smem_u32(
                    B + (ks * 16 + lrow) * BS_STRIDE + wn * 32 + ip * 16 + lcolh);
                uint32_t r0, r1, r2, r3;
                ldm_x4_t(r0, r1, r2, r3, addr);
                b[ip * 2 + 0][0] = r0; b[ip * 2 + 0][1] = r1;
                b[ip * 2 + 1][0] = r2; b[ip * 2 + 1][1] = r3;
            }
            #pragma unroll
            for (int im = 0; im < 4; im++)
                #pragma unroll
                for (int in = 0; in < 4; in++)
                    mma16816(c[im][in][0], c[im][in][1], c[im][in][2], c[im][in][3],
                             a[im][0], a[im][1], a[im][2], a[im][3],
                             b[in][0], b[in][1]);
        }
        __syncthreads();   // all warps done reading A[kt%3], B[kt%2]
        issue(kt + 2);     // writes A[(kt-1)%3] (idle) and B[kt%2] (just fenced)
    }

    // Epilogue
    int gid = lane >> 2, tig = lane & 3;
    #pragma unroll
    for (int im = 0; im < 4; im++) {
        #pragma unroll
        for (int in = 0; in < 4; in++) {
            int row = m0 + wm * 64 + im * 16 + gid;
            int col = wn * 32 + in * 8 + tig * 2;
            if (row < nq) {
                float2 v0 = make_float2(c[im][in][0], c[im][in][1]);
                *(float2*)(out + (size_t)row * COUT + col) = v0;
            }
            if (row + 8 < nq) {
                float2 v1 = make_float2(c[im][in][2], c[im][in][3]);
                *(float2*)(out + (size_t)(row + 8) * COUT + col) = v1;
            }
        }
    }
}

// ---------------------------------------------------------------------------
extern "C" void kernel_launch(void* const* d_in, const int* in_sizes, int n_in,
                              void* d_out, int out_size) {
    const float* qp = (const float*)d_in[0];   // query_points   [N,3]
    const float* sp = (const float*)d_in[1];   // support_points [M,3]
    const int*   ni = (const int*)  d_in[2];   // neighbors_idx  [N,32]
    const float* ft = (const float*)d_in[3];   // features       [M,64]
    const float* kp = (const float*)d_in[4];   // kernel_points  [15,3]
    const float* wt = (const float*)d_in[5];   // wts            [15,64,128]
    float* out = (float*)d_out;

    int nq = in_sizes[0] / 3;
    int m  = in_sizes[1] / 3;

    int prep_elems = m * 16;                    // features dominate (float4 units)
    if (prep_elems < KC * COUT) prep_elems = KC * COUT;
    if (prep_elems < nq) prep_elems = nq;
    prep_kernel<<<(prep_elems + 255) / 256, 256>>>(wt, sp, qp, ft, m, nq);
    weight_kernel<<<(nq + 15) / 16, 128>>>(ni, kp, nq);
    gemm_kernel<<<(nq + 127) / 128, 256>>>(out, nq);
}